// round 9
// baseline (speedup 1.0000x reference)
#include <cuda_runtime.h>
#include <cuda_fp16.h>
#include <math.h>
#include <stdint.h>

// ---------------------------------------------------------------------------
// Problem constants
// ---------------------------------------------------------------------------
#define SRC   2048          // S
#define NB    10            // neighbors
#define DDIM  172           // D
#define EDIM  172           // EDGE
#define TDIM  100           // TD
#define EQ    272           // E  = D + TD
#define KD    444           // D + EDGE + TD
#define KDT   4440          // KD * N
#define HD    136           // head dim (E / H)

#define M0    (SRC*NB)      // 20480 rows prop0
#define M1    SRC           // 2048  rows prop1

// output layout offsets (float elements)
#define OUT_R0    0
#define OUT_R1    (SRC*NB*DDIM)
#define OUT_EDGE  (OUT_R1 + SRC*DDIM)
#define OUT_TD    (OUT_EDGE + SRC*NB*EDIM)

// ---------------------------------------------------------------------------
// Scratch (device globals; no allocation allowed)
// ---------------------------------------------------------------------------
__device__ float g_kvp0[M0 * 544];
__device__ float g_qp0 [M0 * EQ];
__device__ float g_kvp1[M1 * 544];
__device__ float g_qp1 [M1 * EQ];

// fp16 mirrors of GEMM operands
__device__ __half hb_emb0 [SRC*NB*NB*DDIM];
__device__ __half hb_edge0[SRC*NB*NB*EDIM];
__device__ __half hb_td0  [SRC*NB*NB*TDIM];
__device__ __half hb_emb1 [SRC*NB*DDIM];
__device__ __half hb_edge1[SRC*NB*EDIM];
__device__ __half hb_td1  [SRC*NB*TDIM];
__device__ __half hb_emb2 [SRC*DDIM];
__device__ __half hb_Wq[EQ*EQ];
__device__ __half hb_Wk[EQ*KDT];
__device__ __half hb_Wv[EQ*KDT];
__device__ __half hb_Wo[EQ*EQ];
__device__ __half hb_W1[DDIM*(EQ+DDIM)];
__device__ __half hb_W2[DDIM*DDIM];
// fp16 intermediates (GEMM-to-GEMM / attention-to-GEMM)
__device__ __half hb_o0[M0*EQ];
__device__ __half hb_a0[M0*EQ];
__device__ __half hb_h0[M0*DDIM];
__device__ __half hb_o1[M1*EQ];
__device__ __half hb_a1[M1*EQ];
__device__ __half hb_h1[M1*DDIM];

// ---------------------------------------------------------------------------
// fp32 -> fp16 bulk convert (vectorized, n multiple of 4)
// ---------------------------------------------------------------------------
__global__ void cvt16(const float* __restrict__ in, __half* __restrict__ out,
                      int n4)
{
    int i = blockIdx.x * blockDim.x + threadIdx.x;
    if (i < n4) {
        float4 v = reinterpret_cast<const float4*>(in)[i];
        __half2 a = __float22half2_rn(make_float2(v.x, v.y));
        __half2 b = __float22half2_rn(make_float2(v.z, v.w));
        uint2 u;
        u.x = *reinterpret_cast<uint32_t*>(&a);
        u.y = *reinterpret_cast<uint32_t*>(&b);
        reinterpret_cast<uint2*>(out)[i] = u;
    }
}

// ---------------------------------------------------------------------------
// A/B gather address functors (fp16, 4-half chunks; all boundaries %4 == 0)
// ---------------------------------------------------------------------------
template<int MODE>
__device__ __forceinline__ const __half* addrA(const __half* __restrict__ A0,
                                               const __half* __restrict__ A1,
                                               const __half* __restrict__ A2,
                                               int lda, int row, int k)
{
    if (MODE == 0) {
        return A0 + (size_t)row * lda + k;
    } else if (MODE == 1) {
        int n2 = k / KD;
        int f  = k - n2 * KD;
        size_t sub = (size_t)row * NB + n2;
        if (f < DDIM)        return A0 + sub * DDIM + f;
        else if (f < 2*DDIM) return A1 + sub * EDIM + (f - DDIM);
        else                 return A2 + sub * TDIM + (f - 2*DDIM);
    } else if (MODE == 2) {
        if (k < DDIM) return A0 + (size_t)row * DDIM + k;
        else          return A1 + (size_t)row * TDIM + (k - DDIM);
    } else { // MODE == 3
        if (k < EQ)   return A0 + (size_t)row * EQ + k;
        else          return A1 + (size_t)row * DDIM + (k - EQ);
    }
}

template<int MODE>
__device__ __forceinline__ const __half* addrB(const __half* __restrict__ B0,
                                               const __half* __restrict__ B1,
                                               int ldb, int n, int k)
{
    if (MODE == 0) return B0 + (size_t)n * ldb + k;
    if (n < EQ)    return B0 + (size_t)n * KDT + k;
    return B1 + (size_t)(n - EQ) * KDT + k;
}

// ---------------------------------------------------------------------------
// PTX helpers
// ---------------------------------------------------------------------------
__device__ __forceinline__ uint32_t smem_u32(const void* p) {
    uint32_t a;
    asm("{ .reg .u64 t; cvta.to.shared.u64 t, %1; cvt.u32.u64 %0, t; }"
        : "=r"(a) : "l"(p));
    return a;
}

__device__ __forceinline__ void cp_async8(uint32_t smem, const void* gmem,
                                          bool valid) {
    int sz = valid ? 8 : 0;
    asm volatile("cp.async.ca.shared.global [%0], [%1], 8, %2;"
                 :: "r"(smem), "l"(gmem), "r"(sz));
}
#define CP_COMMIT() asm volatile("cp.async.commit_group;")
#define CP_WAIT1()  asm volatile("cp.async.wait_group 1;")

__device__ __forceinline__ void ldsm_x4(uint32_t r[4], uint32_t addr) {
    asm volatile("ldmatrix.sync.aligned.m8n8.x4.shared.b16 {%0,%1,%2,%3}, [%4];"
        : "=r"(r[0]), "=r"(r[1]), "=r"(r[2]), "=r"(r[3]) : "r"(addr));
}

__device__ __forceinline__ void mma_f16(float c[4], const uint32_t a[4],
                                        uint32_t b0, uint32_t b1) {
    asm volatile(
        "mma.sync.aligned.m16n8k16.row.col.f32.f16.f16.f32 "
        "{%0,%1,%2,%3}, {%4,%5,%6,%7}, {%8,%9}, {%0,%1,%2,%3};"
        : "+f"(c[0]), "+f"(c[1]), "+f"(c[2]), "+f"(c[3])
        : "r"(a[0]), "r"(a[1]), "r"(a[2]), "r"(a[3]), "r"(b0), "r"(b1));
}

// ---------------------------------------------------------------------------
// mma.sync fp16 GEMM with 3-stage cp.async pipeline + ldmatrix fragments.
//   C[m,n] = act((sum_k A[m,k]*B[n,k] + bias[n]) * alpha)
// CTA tile 256x64xBK32, 256 threads (8 warps, 4x2), warp tile 64x32.
// Per warp k-step: 6 ldmatrix.x4 feed 16 HMMA (was 4:8 at 32x32 tiles).
// SMEM rows of 32 halves padded to 80 B (16B-aligned rows, conflict-free
// ldmatrix: r*80/16 = 5r mod 8 is a permutation).  M must be %256 == 0
// (holds: M0, M1); K %4 == 0 (holds); N boundary via ZFILL.
// ---------------------------------------------------------------------------
#define STAGES  3
#define ROWB    80
#define A_STG   20480              // 256 * 80
#define B_STG   5120               // 64 * 80
#define B_OFF   (STAGES * A_STG)   // 61440
#define GM_SMEM (B_OFF + STAGES * B_STG)   // 76800

template<int AMODE, int BMODE, bool RELU, bool OUT16>
__global__ void __launch_bounds__(256, 2)
gemm_mma(const __half* __restrict__ A0, const __half* __restrict__ A1,
         const __half* __restrict__ A2, int lda,
         const __half* __restrict__ B0, const __half* __restrict__ B1, int ldb,
         const float* __restrict__ bias0, const float* __restrict__ bias1,
         void* __restrict__ Cv, int M, int N, int K, int ldc, float alpha)
{
    extern __shared__ char sh[];
    const uint32_t sbase = smem_u32(sh);

    const int tid  = threadIdx.x;
    const int wid  = tid >> 5;
    const int lane = tid & 31;
    const int g    = lane >> 2;
    const int t    = lane & 3;
    const int wm   = wid & 3;        // warp m position (0..3) x64 rows
    const int wn   = wid >> 2;       // warp n position (0..1) x32 cols
    const int m0   = blockIdx.y * 256;
    const int n0   = blockIdx.x * 64;

    // ldmatrix per-lane address components (bytes within a stage buffer)
    const uint32_t a_lm = (uint32_t)(wm * 64 + (lane & 7) + ((lane >> 3) & 1) * 8) * ROWB
                        + ((lane >> 4) & 1) * 16;
    const uint32_t b_lm = (uint32_t)(wn * 32 + (lane & 7) + ((lane >> 4) & 1) * 8) * ROWB
                        + ((lane >> 3) & 1) * 16;

    float acc[4][4][4];
#pragma unroll
    for (int i = 0; i < 4; i++)
#pragma unroll
        for (int j = 0; j < 4; j++)
#pragma unroll
            for (int l = 0; l < 4; l++) acc[i][j][l] = 0.f;

    // staging decomposition: thread -> (row group, 4-half chunk)
    const int ar  = tid >> 3;        // rows 0..31 (+32 per step)
    const int akq = tid & 7;         // chunk index within 32-half row
    const int KT  = (K + 31) / 32;

#define ISSUE(st_, k0_)                                                        \
    do {                                                                       \
        const uint32_t abase = sbase + (st_) * A_STG;                          \
        const uint32_t bbase = sbase + B_OFF + (st_) * B_STG;                  \
        const int gk = (k0_) + akq * 4;                                        \
        const bool kval = gk < K;                                              \
        const int gksafe = kval ? gk : 0;                                      \
        _Pragma("unroll")                                                      \
        for (int p = 0; p < 8; p++) {                                          \
            int r = ar + p * 32;                                               \
            const __half* src = addrA<AMODE>(A0, A1, A2, lda, m0 + r, gksafe); \
            cp_async8(abase + r * ROWB + akq * 8, src, kval);                  \
        }                                                                      \
        _Pragma("unroll")                                                      \
        for (int p = 0; p < 2; p++) {                                          \
            int r = ar + p * 32, gn = n0 + r;                                  \
            bool v = kval && (gn < N);                                         \
            const __half* src = addrB<BMODE>(B0, B1, ldb, v ? gn : 0, gksafe); \
            cp_async8(bbase + r * ROWB + akq * 8, src, v);                     \
        }                                                                      \
    } while (0)

    // prologue: stages 0 and 1 in flight
    ISSUE(0, 0);  CP_COMMIT();
    ISSUE(1, 32); CP_COMMIT();
    CP_WAIT1();                      // stage 0 ready
    __syncthreads();

    int st = 0;
    for (int it = 0; it < KT; ++it) {
        // issue loads for stage it+2 (overlaps compute below)
        int st2 = st + 2; if (st2 >= STAGES) st2 -= STAGES;
        if (it + 2 < KT) ISSUE(st2, (it + 2) * 32);
        CP_COMMIT();

        // compute on stage st
        const uint32_t Abu = sbase + st * A_STG + a_lm;
        const uint32_t Bbu = sbase + B_OFF + st * B_STG + b_lm;
#pragma unroll
        for (int ks = 0; ks < 2; ks++) {
            uint32_t af[4][4], bq[2][4];
#pragma unroll
            for (int mt = 0; mt < 4; mt++)
                ldsm_x4(af[mt], Abu + mt * (16 * ROWB) + ks * 32);
#pragma unroll
            for (int ntp = 0; ntp < 2; ntp++)
                ldsm_x4(bq[ntp], Bbu + ntp * (16 * ROWB) + ks * 32);
#pragma unroll
            for (int mt = 0; mt < 4; mt++)
#pragma unroll
                for (int ntp = 0; ntp < 2; ntp++) {
                    mma_f16(acc[mt][2*ntp + 0], af[mt], bq[ntp][0], bq[ntp][1]);
                    mma_f16(acc[mt][2*ntp + 1], af[mt], bq[ntp][2], bq[ntp][3]);
                }
        }

        CP_WAIT1();                  // next stage ready
        __syncthreads();
        if (++st >= STAGES) st = 0;
    }

    // ---- epilogue ----
#pragma unroll
    for (int mt = 0; mt < 4; mt++) {
        int row0 = m0 + wm * 64 + mt * 16 + g;
#pragma unroll
        for (int nt = 0; nt < 4; nt++) {
            int col = n0 + wn * 32 + nt * 8 + t * 2;
#pragma unroll
            for (int half_ = 0; half_ < 2; half_++) {
                int gm = row0 + half_ * 8;
                if (gm >= M) continue;
#pragma unroll
                for (int cc = 0; cc < 2; cc++) {
                    int gn = col + cc;
                    if (gn >= N) continue;
                    float bval = (BMODE == 1)
                               ? (gn < EQ ? bias0[gn] : bias1[gn - EQ])
                               : bias0[gn];
                    float v = (acc[mt][nt][half_ * 2 + cc] + bval) * alpha;
                    if (RELU) v = fmaxf(v, 0.f);
                    if (OUT16)
                        ((__half*)Cv)[(size_t)gm * ldc + gn] = __float2half(v);
                    else
                        ((float*)Cv)[(size_t)gm * ldc + gn] = v;
                }
            }
        }
    }
#undef ISSUE
}

// ---------------------------------------------------------------------------
// Attention prop0: per node, 2 heads, 10x10, hd=136.  Emits fp16 o.
// ---------------------------------------------------------------------------
__global__ void __launch_bounds__(256)
attn0_kernel(const float* __restrict__ qp, const float* __restrict__ kvp,
             __half* __restrict__ o)
{
    __shared__ float Qs[NB][EQ];
    __shared__ float Ks[NB][EQ];
    __shared__ float Vs[NB][EQ];
    __shared__ float P[2][NB][NB];

    const int s = blockIdx.x;
    const int tid = threadIdx.x;
    const size_t base = (size_t)s * NB;

    for (int i = tid; i < NB * EQ; i += 256) {
        int r = i / EQ, f = i - r * EQ;
        Qs[r][f] = qp[(base + r) * EQ + f];
        Ks[r][f] = kvp[(base + r) * 544 + f];
        Vs[r][f] = kvp[(base + r) * 544 + EQ + f];
    }
    __syncthreads();

    if (tid < 200) {
        int h = tid / 100, rem = tid - h * 100;
        int qi = rem / NB, ki = rem - qi * NB;
        const float* q = &Qs[qi][h * HD];
        const float* k = &Ks[ki][h * HD];
        float acc = 0.f;
#pragma unroll 8
        for (int d = 0; d < HD; d++) acc = fmaf(q[d], k[d], acc);
        P[h][qi][ki] = acc;
    }
    __syncthreads();

    if (tid < 20) {
        int h = tid / NB, qi = tid - h * NB;
        float mx = -1e30f;
#pragma unroll
        for (int ki = 0; ki < NB; ki++) mx = fmaxf(mx, P[h][qi][ki]);
        float sum = 0.f;
#pragma unroll
        for (int ki = 0; ki < NB; ki++) {
            float e = expf(P[h][qi][ki] - mx);
            P[h][qi][ki] = e;
            sum += e;
        }
        float inv = 1.f / sum;
#pragma unroll
        for (int ki = 0; ki < NB; ki++) P[h][qi][ki] *= inv;
    }
    __syncthreads();

    for (int i = tid; i < NB * EQ; i += 256) {
        int qi = i / EQ, f = i - qi * EQ;
        int h = f / HD;
        float acc = 0.f;
#pragma unroll
        for (int ki = 0; ki < NB; ki++) acc = fmaf(P[h][qi][ki], Vs[ki][f], acc);
        o[(base + qi) * EQ + f] = __float2half(acc);
    }
}

// ---------------------------------------------------------------------------
// Attention prop1: full 2048x2048, flash-style online softmax.  Emits fp16 o.
// ---------------------------------------------------------------------------
#define A1_BQ   32
#define A1_BK   64
#define A1_KP   137
#define A1_PP   65
#define A1_SMEM_FLOATS (A1_BQ*HD + 2*A1_BK*A1_KP + A1_BQ*A1_PP + 3*A1_BQ)

__global__ void __launch_bounds__(256)
attn1_kernel(const float* __restrict__ qp, const float* __restrict__ kvp,
             __half* __restrict__ o)
{
    extern __shared__ float sm[];
    float* Qs = sm;
    float* Ksm = Qs + A1_BQ * HD;
    float* Vsm = Ksm + A1_BK * A1_KP;
    float* Ps  = Vsm + A1_BK * A1_KP;
    float* m_s = Ps + A1_BQ * A1_PP;
    float* l_s = m_s + A1_BQ;
    float* al_s = l_s + A1_BQ;

    const int h  = blockIdx.y;
    const int q0 = blockIdx.x * A1_BQ;
    const int tid = threadIdx.x;

    for (int i = tid; i < A1_BQ * HD; i += 256) {
        int r = i / HD, d = i - r * HD;
        Qs[r * HD + d] = qp[(size_t)(q0 + r) * EQ + h * HD + d];
    }
    if (tid < A1_BQ) { m_s[tid] = -1e30f; l_s[tid] = 0.f; }

    const int qown = tid >> 3;
    const int dg   = tid & 7;
    const int tyq  = tid >> 5;
    const int txk  = tid & 31;

    float oacc[17];
#pragma unroll
    for (int j = 0; j < 17; j++) oacc[j] = 0.f;

    for (int kt = 0; kt < SRC; kt += A1_BK) {
        __syncthreads();
        for (int i = tid; i < A1_BK * HD; i += 256) {
            int r = i / HD, d = i - r * HD;
            Ksm[r * A1_KP + d] = kvp[(size_t)(kt + r) * 544 + h * HD + d];
            Vsm[r * A1_KP + d] = kvp[(size_t)(kt + r) * 544 + EQ + h * HD + d];
        }
        __syncthreads();

        float sc[4][2];
#pragma unroll
        for (int i = 0; i < 4; i++) { sc[i][0] = 0.f; sc[i][1] = 0.f; }
        const float* krow0 = &Ksm[(txk * 2 + 0) * A1_KP];
        const float* krow1 = &Ksm[(txk * 2 + 1) * A1_KP];
#pragma unroll 4
        for (int d = 0; d < HD; d++) {
            float kv0 = krow0[d];
            float kv1 = krow1[d];
#pragma unroll
            for (int i = 0; i < 4; i++) {
                float qv = Qs[(tyq * 4 + i) * HD + d];
                sc[i][0] = fmaf(qv, kv0, sc[i][0]);
                sc[i][1] = fmaf(qv, kv1, sc[i][1]);
            }
        }
#pragma unroll
        for (int i = 0; i < 4; i++) {
            Ps[(tyq * 4 + i) * A1_PP + txk * 2 + 0] = sc[i][0];
            Ps[(tyq * 4 + i) * A1_PP + txk * 2 + 1] = sc[i][1];
        }
        __syncthreads();

        if (tid < A1_BQ) {
            float mx = m_s[tid];
            float* prow = &Ps[tid * A1_PP];
#pragma unroll 8
            for (int j = 0; j < A1_BK; j++) mx = fmaxf(mx, prow[j]);
            float al = expf(m_s[tid] - mx);
            float sum = 0.f;
#pragma unroll 8
            for (int j = 0; j < A1_BK; j++) {
                float e = expf(prow[j] - mx);
                prow[j] = e;
                sum += e;
            }
            l_s[tid] = l_s[tid] * al + sum;
            m_s[tid] = mx;
            al_s[tid] = al;
        }
        __syncthreads();

        float al = al_s[qown];
#pragma unroll
        for (int j = 0; j < 17; j++) oacc[j] *= al;
        const float* prow = &Ps[qown * A1_PP];
#pragma unroll 2
        for (int ki = 0; ki < A1_BK; ki++) {
            float p = prow[ki];
            const float* vrow = &Vsm[ki * A1_KP + dg * 17];
#pragma unroll
            for (int j = 0; j < 17; j++) oacc[j] = fmaf(p, vrow[j], oacc[j]);
        }
    }

    float inv = 1.f / l_s[qown];
#pragma unroll
    for (int j = 0; j < 17; j++)
        o[(size_t)(q0 + qown) * EQ + h * HD + dg * 17 + j] =
            __float2half(oacc[j] * inv);
}

// ---------------------------------------------------------------------------
// Host launch
// ---------------------------------------------------------------------------
static inline void launch_cvt(const float* in, __half* out, size_t n) {
    int n4 = (int)(n / 4);
    cvt16<<<(n4 + 255) / 256, 256>>>(in, out, n4);
}

extern "C" void kernel_launch(void* const* d_in, const int* in_sizes, int n_in,
                              void* d_out, int out_size)
{
    const float* emb0  = (const float*)d_in[0];
    const float* edge0 = (const float*)d_in[1];
    const float* td0   = (const float*)d_in[2];
    const float* emb1  = (const float*)d_in[3];
    const float* edge1 = (const float*)d_in[4];
    const float* td1   = (const float*)d_in[5];
    const float* emb2  = (const float*)d_in[6];
    const float* Wq    = (const float*)d_in[7];
    const float* bq    = (const float*)d_in[8];
    const float* Wk    = (const float*)d_in[9];
    const float* bk    = (const float*)d_in[10];
    const float* Wv    = (const float*)d_in[11];
    const float* bv    = (const float*)d_in[12];
    const float* Wo    = (const float*)d_in[13];
    const float* bo    = (const float*)d_in[14];
    const float* W1    = (const float*)d_in[15];
    const float* b1    = (const float*)d_in[16];
    const float* W2    = (const float*)d_in[17];
    const float* b2    = (const float*)d_in[18];
    float* out = (float*)d_out;

    float *kvp0, *qp0, *kvp1, *qp1;
    cudaGetSymbolAddress((void**)&kvp0, g_kvp0);
    cudaGetSymbolAddress((void**)&qp0,  g_qp0);
    cudaGetSymbolAddress((void**)&kvp1, g_kvp1);
    cudaGetSymbolAddress((void**)&qp1,  g_qp1);

    __half *he0, *hg0, *ht0, *he1, *hg1, *ht1, *he2;
    __half *hWq, *hWk, *hWv, *hWo, *hW1, *hW2;
    __half *ho0, *ha0, *hh0, *ho1, *ha1, *hh1;
    cudaGetSymbolAddress((void**)&he0, hb_emb0);
    cudaGetSymbolAddress((void**)&hg0, hb_edge0);
    cudaGetSymbolAddress((void**)&ht0, hb_td0);
    cudaGetSymbolAddress((void**)&he1, hb_emb1);
    cudaGetSymbolAddress((void**)&hg1, hb_edge1);
    cudaGetSymbolAddress((void**)&ht1, hb_td1);
    cudaGetSymbolAddress((void**)&he2, hb_emb2);
    cudaGetSymbolAddress((void**)&hWq, hb_Wq);
    cudaGetSymbolAddress((void**)&hWk, hb_Wk);
    cudaGetSymbolAddress((void**)&hWv, hb_Wv);
    cudaGetSymbolAddress((void**)&hWo, hb_Wo);
    cudaGetSymbolAddress((void**)&hW1, hb_W1);
    cudaGetSymbolAddress((void**)&hW2, hb_W2);
    cudaGetSymbolAddress((void**)&ho0, hb_o0);
    cudaGetSymbolAddress((void**)&ha0, hb_a0);
    cudaGetSymbolAddress((void**)&hh0, hb_h0);
    cudaGetSymbolAddress((void**)&ho1, hb_o1);
    cudaGetSymbolAddress((void**)&ha1, hb_a1);
    cudaGetSymbolAddress((void**)&hh1, hb_h1);

    const float scale = 1.0f / sqrtf((float)HD);
    const int smem1 = A1_SMEM_FLOATS * (int)sizeof(float);
    cudaFuncSetAttribute(attn1_kernel,
                         cudaFuncAttributeMaxDynamicSharedMemorySize, smem1);
    cudaFuncSetAttribute(gemm_mma<1, 1, false, false>,
                         cudaFuncAttributeMaxDynamicSharedMemorySize, GM_SMEM);
    cudaFuncSetAttribute(gemm_mma<2, 0, false, false>,
                         cudaFuncAttributeMaxDynamicSharedMemorySize, GM_SMEM);
    cudaFuncSetAttribute(gemm_mma<0, 0, false, true>,
                         cudaFuncAttributeMaxDynamicSharedMemorySize, GM_SMEM);
    cudaFuncSetAttribute(gemm_mma<3, 0, true, true>,
                         cudaFuncAttributeMaxDynamicSharedMemorySize, GM_SMEM);
    cudaFuncSetAttribute(gemm_mma<0, 0, false, false>,
                         cudaFuncAttributeMaxDynamicSharedMemorySize, GM_SMEM);

    // ---------------- fp16 conversions (once per replay) ----------------
    launch_cvt(emb0,  he0, (size_t)SRC*NB*NB*DDIM);
    launch_cvt(edge0, hg0, (size_t)SRC*NB*NB*EDIM);
    launch_cvt(td0,   ht0, (size_t)SRC*NB*NB*TDIM);
    launch_cvt(emb1,  he1, (size_t)SRC*NB*DDIM);
    launch_cvt(edge1, hg1, (size_t)SRC*NB*EDIM);
    launch_cvt(td1,   ht1, (size_t)SRC*NB*TDIM);
    launch_cvt(emb2,  he2, (size_t)SRC*DDIM);
    launch_cvt(Wq, hWq, (size_t)EQ*EQ);
    launch_cvt(Wk, hWk, (size_t)EQ*KDT);
    launch_cvt(Wv, hWv, (size_t)EQ*KDT);
    launch_cvt(Wo, hWo, (size_t)EQ*EQ);
    launch_cvt(W1, hW1, (size_t)DDIM*(EQ+DDIM));
    launch_cvt(W2, hW2, (size_t)DDIM*DDIM);

    // ---------------- propagation 0 (M0/256 = 80 row blocks) -------------
    gemm_mma<1, 1, false, false><<<dim3(9, 80), 256, GM_SMEM>>>(
        he0, hg0, ht0, 0, hWk, hWv, KDT, bk, bv,
        kvp0, M0, 544, KDT, 544, 1.f);
    gemm_mma<2, 0, false, false><<<dim3(5, 80), 256, GM_SMEM>>>(
        he1, ht1, nullptr, 0, hWq, nullptr, EQ, bq, nullptr,
        qp0, M0, EQ, EQ, EQ, scale);
    attn0_kernel<<<SRC, 256>>>(qp0, kvp0, ho0);
    gemm_mma<0, 0, false, true><<<dim3(5, 80), 256, GM_SMEM>>>(
        ho0, nullptr, nullptr, EQ, hWo, nullptr, EQ, bo, nullptr,
        ha0, M0, EQ, EQ, EQ, 1.f);
    gemm_mma<3, 0, true, true><<<dim3(3, 80), 256, GM_SMEM>>>(
        ha0, he1, nullptr, 0, hW1, nullptr, EQ + DDIM, b1, nullptr,
        hh0, M0, DDIM, EQ + DDIM, DDIM, 1.f);
    gemm_mma<0, 0, false, false><<<dim3(3, 80), 256, GM_SMEM>>>(
        hh0, nullptr, nullptr, DDIM, hW2, nullptr, DDIM, b2, nullptr,
        out + OUT_R0, M0, DDIM, DDIM, DDIM, 1.f);

    // ---------------- propagation 1 (M1/256 = 8 row blocks) --------------
    gemm_mma<1, 1, false, false><<<dim3(9, 8), 256, GM_SMEM>>>(
        he1, hg1, ht1, 0, hWk, hWv, KDT, bk, bv,
        kvp1, M1, 544, KDT, 544, 1.f);
    gemm_mma<0, 0, false, false><<<dim3(5, 8), 256, GM_SMEM>>>(
        he2, nullptr, nullptr, DDIM, hWq, nullptr, EQ, bq, nullptr,
        qp1, M1, EQ, DDIM, EQ, scale);
    attn1_kernel<<<dim3(SRC / A1_BQ, 2), 256, smem1>>>(qp1, kvp1, ho1);
    gemm_mma<0, 0, false, true><<<dim3(5, 8), 256, GM_SMEM>>>(
        ho1, nullptr, nullptr, EQ, hWo, nullptr, EQ, bo, nullptr,
        ha1, M1, EQ, EQ, EQ, 1.f);
    gemm_mma<3, 0, true, true><<<dim3(3, 8), 256, GM_SMEM>>>(
        ha1, he2, nullptr, 0, hW1, nullptr, EQ + DDIM, b1, nullptr,
        hh1, M1, DDIM, EQ + DDIM, DDIM, 1.f);
    gemm_mma<0, 0, false, false><<<dim3(3, 8), 256, GM_SMEM>>>(
        hh1, nullptr, nullptr, DDIM, hW2, nullptr, DDIM, b2, nullptr,
        out + OUT_R1, M1, DDIM, DDIM, DDIM, 1.f);

    // ---------------- passthrough outputs ----------------
    cudaMemcpyAsync(out + OUT_EDGE, edge1, (size_t)SRC * NB * EDIM * sizeof(float),
                    cudaMemcpyDeviceToDevice);
    cudaMemcpyAsync(out + OUT_TD, td1, (size_t)SRC * NB * TDIM * sizeof(float),
                    cudaMemcpyDeviceToDevice);
}

// round 11
// speedup vs baseline: 1.0078x; 1.0078x over previous
#include <cuda_runtime.h>
#include <cuda_fp16.h>
#include <math.h>
#include <stdint.h>

// ---------------------------------------------------------------------------
// Problem constants
// ---------------------------------------------------------------------------
#define SRC   2048          // S
#define NB    10            // neighbors
#define DDIM  172           // D
#define EDIM  172           // EDGE
#define TDIM  100           // TD
#define EQ    272           // E  = D + TD
#define KD    444           // D + EDGE + TD
#define KDT   4440          // KD * N
#define HD    136           // head dim (E / H)

#define M0    (SRC*NB)      // 20480 rows prop0
#define M1    SRC           // 2048  rows prop1

// output layout offsets (float elements)
#define OUT_R0    0
#define OUT_R1    (SRC*NB*DDIM)
#define OUT_EDGE  (OUT_R1 + SRC*DDIM)
#define OUT_TD    (OUT_EDGE + SRC*NB*EDIM)

// ---------------------------------------------------------------------------
// Scratch (device globals; no allocation allowed)
// ---------------------------------------------------------------------------
__device__ float g_kvp0[M0 * 544];
__device__ float g_qp0 [M0 * EQ];
__device__ float g_kvp1[M1 * 544];
__device__ float g_qp1 [M1 * EQ];

// fp16 mirrors of GEMM operands
__device__ __half hb_emb0 [SRC*NB*NB*DDIM];
__device__ __half hb_edge0[SRC*NB*NB*EDIM];
__device__ __half hb_td0  [SRC*NB*NB*TDIM];
__device__ __half hb_emb1 [SRC*NB*DDIM];
__device__ __half hb_edge1[SRC*NB*EDIM];
__device__ __half hb_td1  [SRC*NB*TDIM];
__device__ __half hb_emb2 [SRC*DDIM];
__device__ __half hb_Wq[EQ*EQ];
__device__ __half hb_Wk[EQ*KDT];
__device__ __half hb_Wv[EQ*KDT];
__device__ __half hb_Wo[EQ*EQ];
__device__ __half hb_W1[DDIM*(EQ+DDIM)];
__device__ __half hb_W2[DDIM*DDIM];
// fp16 intermediates (GEMM-to-GEMM / attention-to-GEMM)
__device__ __half hb_o0[M0*EQ];
__device__ __half hb_a0[M0*EQ];
__device__ __half hb_h0[M0*DDIM];
__device__ __half hb_o1[M1*EQ];
__device__ __half hb_a1[M1*EQ];
__device__ __half hb_h1[M1*DDIM];

// ---------------------------------------------------------------------------
// fp32 -> fp16 bulk convert (vectorized, n multiple of 4)
// ---------------------------------------------------------------------------
__global__ void cvt16(const float* __restrict__ in, __half* __restrict__ out,
                      int n4)
{
    int i = blockIdx.x * blockDim.x + threadIdx.x;
    if (i < n4) {
        float4 v = reinterpret_cast<const float4*>(in)[i];
        __half2 a = __float22half2_rn(make_float2(v.x, v.y));
        __half2 b = __float22half2_rn(make_float2(v.z, v.w));
        uint2 u;
        u.x = *reinterpret_cast<uint32_t*>(&a);
        u.y = *reinterpret_cast<uint32_t*>(&b);
        reinterpret_cast<uint2*>(out)[i] = u;
    }
}

// ---------------------------------------------------------------------------
// A/B gather address functors (fp16, 4-half chunks; all boundaries %4 == 0)
// ---------------------------------------------------------------------------
template<int MODE>
__device__ __forceinline__ const __half* addrA(const __half* __restrict__ A0,
                                               const __half* __restrict__ A1,
                                               const __half* __restrict__ A2,
                                               int lda, int row, int k)
{
    if (MODE == 0) {
        return A0 + (size_t)row * lda + k;
    } else if (MODE == 1) {
        int n2 = k / KD;
        int f  = k - n2 * KD;
        size_t sub = (size_t)row * NB + n2;
        if (f < DDIM)        return A0 + sub * DDIM + f;
        else if (f < 2*DDIM) return A1 + sub * EDIM + (f - DDIM);
        else                 return A2 + sub * TDIM + (f - 2*DDIM);
    } else if (MODE == 2) {
        if (k < DDIM) return A0 + (size_t)row * DDIM + k;
        else          return A1 + (size_t)row * TDIM + (k - DDIM);
    } else { // MODE == 3
        if (k < EQ)   return A0 + (size_t)row * EQ + k;
        else          return A1 + (size_t)row * DDIM + (k - EQ);
    }
}

template<int MODE>
__device__ __forceinline__ const __half* addrB(const __half* __restrict__ B0,
                                               const __half* __restrict__ B1,
                                               int ldb, int n, int k)
{
    if (MODE == 0) return B0 + (size_t)n * ldb + k;
    if (n < EQ)    return B0 + (size_t)n * KDT + k;
    return B1 + (size_t)(n - EQ) * KDT + k;
}

// ---------------------------------------------------------------------------
// PTX helpers
// ---------------------------------------------------------------------------
__device__ __forceinline__ uint32_t smem_u32(const void* p) {
    uint32_t a;
    asm("{ .reg .u64 t; cvta.to.shared.u64 t, %1; cvt.u32.u64 %0, t; }"
        : "=r"(a) : "l"(p));
    return a;
}

__device__ __forceinline__ void cp_async8(uint32_t smem, const void* gmem,
                                          bool valid) {
    int sz = valid ? 8 : 0;
    asm volatile("cp.async.ca.shared.global [%0], [%1], 8, %2;"
                 :: "r"(smem), "l"(gmem), "r"(sz));
}
#define CP_COMMIT() asm volatile("cp.async.commit_group;")
#define CP_WAIT1()  asm volatile("cp.async.wait_group 1;")

__device__ __forceinline__ void ldsm_x4(uint32_t r[4], uint32_t addr) {
    asm volatile("ldmatrix.sync.aligned.m8n8.x4.shared.b16 {%0,%1,%2,%3}, [%4];"
        : "=r"(r[0]), "=r"(r[1]), "=r"(r[2]), "=r"(r[3]) : "r"(addr));
}

__device__ __forceinline__ void mma_f16(float c[4], const uint32_t a[4],
                                        uint32_t b0, uint32_t b1) {
    asm volatile(
        "mma.sync.aligned.m16n8k16.row.col.f32.f16.f16.f32 "
        "{%0,%1,%2,%3}, {%4,%5,%6,%7}, {%8,%9}, {%0,%1,%2,%3};"
        : "+f"(c[0]), "+f"(c[1]), "+f"(c[2]), "+f"(c[3])
        : "r"(a[0]), "r"(a[1]), "r"(a[2]), "r"(a[3]), "r"(b0), "r"(b1));
}

// ---------------------------------------------------------------------------
// mma.sync fp16 GEMM with 3-stage cp.async pipeline + ldmatrix fragments.
//   C[m,n] = act((sum_k A[m,k]*B[n,k] + bias[n]) * alpha)
// CTA tile 128x64xBK32, 256 threads (8 warps, 4x2), warp tile 32x32.
// SMEM rows of 32 halves padded to 80 B (16B-aligned rows, conflict-free
// ldmatrix: r*80/16 = 5r mod 8 is a permutation).  M %128 == 0 holds;
// K %4 == 0 holds; N boundary via ZFILL.
// ---------------------------------------------------------------------------
#define STAGES  3
#define ROWB    80
#define A_STG   10240              // 128 * 80
#define B_STG   5120               // 64 * 80
#define B_OFF   (STAGES * A_STG)   // 30720
#define GM_SMEM (B_OFF + STAGES * B_STG)   // 46080

template<int AMODE, int BMODE, bool RELU, bool OUT16>
__global__ void __launch_bounds__(256)
gemm_mma(const __half* __restrict__ A0, const __half* __restrict__ A1,
         const __half* __restrict__ A2, int lda,
         const __half* __restrict__ B0, const __half* __restrict__ B1, int ldb,
         const float* __restrict__ bias0, const float* __restrict__ bias1,
         void* __restrict__ Cv, int M, int N, int K, int ldc, float alpha)
{
    extern __shared__ char sh[];
    const uint32_t sbase = smem_u32(sh);

    const int tid  = threadIdx.x;
    const int wid  = tid >> 5;
    const int lane = tid & 31;
    const int g    = lane >> 2;
    const int t    = lane & 3;
    const int wm   = wid & 3;        // warp m position (0..3) x32 rows
    const int wn   = wid >> 2;       // warp n position (0..1) x32 cols
    const int m0   = blockIdx.y * 128;
    const int n0   = blockIdx.x * 64;

    // ldmatrix per-lane address components (bytes within a stage buffer)
    const uint32_t a_lm = (uint32_t)(wm * 32 + (lane & 7) + ((lane >> 3) & 1) * 8) * ROWB
                        + ((lane >> 4) & 1) * 16;
    const uint32_t b_lm = (uint32_t)(wn * 32 + (lane & 7) + ((lane >> 4) & 1) * 8) * ROWB
                        + ((lane >> 3) & 1) * 16;

    float acc[2][4][4];
#pragma unroll
    for (int i = 0; i < 2; i++)
#pragma unroll
        for (int j = 0; j < 4; j++)
#pragma unroll
            for (int l = 0; l < 4; l++) acc[i][j][l] = 0.f;

    // staging decomposition: thread -> (row group, 4-half chunk)
    const int ar  = tid >> 3;        // rows 0..31 (+32 per step)
    const int akq = tid & 7;         // chunk index within 32-half row
    const int KT  = (K + 31) / 32;

#define ISSUE(st_, k0_)                                                        \
    do {                                                                       \
        const uint32_t abase = sbase + (st_) * A_STG;                          \
        const uint32_t bbase = sbase + B_OFF + (st_) * B_STG;                  \
        const int gk = (k0_) + akq * 4;                                        \
        const bool kval = gk < K;                                              \
        const int gksafe = kval ? gk : 0;                                      \
        _Pragma("unroll")                                                      \
        for (int p = 0; p < 4; p++) {                                          \
            int r = ar + p * 32;                                               \
            const __half* src = addrA<AMODE>(A0, A1, A2, lda, m0 + r, gksafe); \
            cp_async8(abase + r * ROWB + akq * 8, src, kval);                  \
        }                                                                      \
        _Pragma("unroll")                                                      \
        for (int p = 0; p < 2; p++) {                                          \
            int r = ar + p * 32, gn = n0 + r;                                  \
            bool v = kval && (gn < N);                                         \
            const __half* src = addrB<BMODE>(B0, B1, ldb, v ? gn : 0, gksafe); \
            cp_async8(bbase + r * ROWB + akq * 8, src, v);                     \
        }                                                                      \
    } while (0)

    // prologue: stages 0 and 1 in flight
    ISSUE(0, 0);  CP_COMMIT();
    ISSUE(1, 32); CP_COMMIT();
    CP_WAIT1();                      // stage 0 ready
    __syncthreads();

    int st = 0;
    for (int it = 0; it < KT; ++it) {
        // issue loads for stage it+2 (overlaps compute below)
        int st2 = st + 2; if (st2 >= STAGES) st2 -= STAGES;
        if (it + 2 < KT) ISSUE(st2, (it + 2) * 32);
        CP_COMMIT();

        // compute on stage st
        const uint32_t Abu = sbase + st * A_STG + a_lm;
        const uint32_t Bbu = sbase + B_OFF + st * B_STG + b_lm;
#pragma unroll
        for (int ks = 0; ks < 2; ks++) {
            uint32_t af[2][4], bq[2][4];
#pragma unroll
            for (int mt = 0; mt < 2; mt++)
                ldsm_x4(af[mt], Abu + mt * (16 * ROWB) + ks * 32);
#pragma unroll
            for (int ntp = 0; ntp < 2; ntp++)
                ldsm_x4(bq[ntp], Bbu + ntp * (16 * ROWB) + ks * 32);
#pragma unroll
            for (int mt = 0; mt < 2; mt++)
#pragma unroll
                for (int ntp = 0; ntp < 2; ntp++) {
                    mma_f16(acc[mt][2*ntp + 0], af[mt], bq[ntp][0], bq[ntp][1]);
                    mma_f16(acc[mt][2*ntp + 1], af[mt], bq[ntp][2], bq[ntp][3]);
                }
        }

        CP_WAIT1();                  // next stage ready
        __syncthreads();
        if (++st >= STAGES) st = 0;
    }

    // ---- epilogue ----
#pragma unroll
    for (int mt = 0; mt < 2; mt++) {
        int row0 = m0 + wm * 32 + mt * 16 + g;
#pragma unroll
        for (int nt = 0; nt < 4; nt++) {
            int col = n0 + wn * 32 + nt * 8 + t * 2;
#pragma unroll
            for (int half_ = 0; half_ < 2; half_++) {
                int gm = row0 + half_ * 8;
                if (gm >= M) continue;
#pragma unroll
                for (int cc = 0; cc < 2; cc++) {
                    int gn = col + cc;
                    if (gn >= N) continue;
                    float bval = (BMODE == 1)
                               ? (gn < EQ ? bias0[gn] : bias1[gn - EQ])
                               : bias0[gn];
                    float v = (acc[mt][nt][half_ * 2 + cc] + bval) * alpha;
                    if (RELU) v = fmaxf(v, 0.f);
                    if (OUT16)
                        ((__half*)Cv)[(size_t)gm * ldc + gn] = __float2half(v);
                    else
                        ((float*)Cv)[(size_t)gm * ldc + gn] = v;
                }
            }
        }
    }
#undef ISSUE
}

// ---------------------------------------------------------------------------
// Attention prop0: per node, 2 heads, 10x10, hd=136.  Emits fp16 o.
// ---------------------------------------------------------------------------
__global__ void __launch_bounds__(256)
attn0_kernel(const float* __restrict__ qp, const float* __restrict__ kvp,
             __half* __restrict__ o)
{
    __shared__ float Qs[NB][EQ];
    __shared__ float Ks[NB][EQ];
    __shared__ float Vs[NB][EQ];
    __shared__ float P[2][NB][NB];

    const int s = blockIdx.x;
    const int tid = threadIdx.x;
    const size_t base = (size_t)s * NB;

    for (int i = tid; i < NB * EQ; i += 256) {
        int r = i / EQ, f = i - r * EQ;
        Qs[r][f] = qp[(base + r) * EQ + f];
        Ks[r][f] = kvp[(base + r) * 544 + f];
        Vs[r][f] = kvp[(base + r) * 544 + EQ + f];
    }
    __syncthreads();

    if (tid < 200) {
        int h = tid / 100, rem = tid - h * 100;
        int qi = rem / NB, ki = rem - qi * NB;
        const float* q = &Qs[qi][h * HD];
        const float* k = &Ks[ki][h * HD];
        float acc = 0.f;
#pragma unroll 8
        for (int d = 0; d < HD; d++) acc = fmaf(q[d], k[d], acc);
        P[h][qi][ki] = acc;
    }
    __syncthreads();

    if (tid < 20) {
        int h = tid / NB, qi = tid - h * NB;
        float mx = -1e30f;
#pragma unroll
        for (int ki = 0; ki < NB; ki++) mx = fmaxf(mx, P[h][qi][ki]);
        float sum = 0.f;
#pragma unroll
        for (int ki = 0; ki < NB; ki++) {
            float e = expf(P[h][qi][ki] - mx);
            P[h][qi][ki] = e;
            sum += e;
        }
        float inv = 1.f / sum;
#pragma unroll
        for (int ki = 0; ki < NB; ki++) P[h][qi][ki] *= inv;
    }
    __syncthreads();

    for (int i = tid; i < NB * EQ; i += 256) {
        int qi = i / EQ, f = i - qi * EQ;
        int h = f / HD;
        float acc = 0.f;
#pragma unroll
        for (int ki = 0; ki < NB; ki++) acc = fmaf(P[h][qi][ki], Vs[ki][f], acc);
        o[(base + qi) * EQ + f] = __float2half(acc);
    }
}

// ---------------------------------------------------------------------------
// Attention prop1: full 2048x2048, flash-style online softmax.  Emits fp16 o.
// ---------------------------------------------------------------------------
#define A1_BQ   32
#define A1_BK   64
#define A1_KP   137
#define A1_PP   65
#define A1_SMEM_FLOATS (A1_BQ*HD + 2*A1_BK*A1_KP + A1_BQ*A1_PP + 3*A1_BQ)

__global__ void __launch_bounds__(256)
attn1_kernel(const float* __restrict__ qp, const float* __restrict__ kvp,
             __half* __restrict__ o)
{
    extern __shared__ float sm[];
    float* Qs = sm;
    float* Ksm = Qs + A1_BQ * HD;
    float* Vsm = Ksm + A1_BK * A1_KP;
    float* Ps  = Vsm + A1_BK * A1_KP;
    float* m_s = Ps + A1_BQ * A1_PP;
    float* l_s = m_s + A1_BQ;
    float* al_s = l_s + A1_BQ;

    const int h  = blockIdx.y;
    const int q0 = blockIdx.x * A1_BQ;
    const int tid = threadIdx.x;

    for (int i = tid; i < A1_BQ * HD; i += 256) {
        int r = i / HD, d = i - r * HD;
        Qs[r * HD + d] = qp[(size_t)(q0 + r) * EQ + h * HD + d];
    }
    if (tid < A1_BQ) { m_s[tid] = -1e30f; l_s[tid] = 0.f; }

    const int qown = tid >> 3;
    const int dg   = tid & 7;
    const int tyq  = tid >> 5;
    const int txk  = tid & 31;

    float oacc[17];
#pragma unroll
    for (int j = 0; j < 17; j++) oacc[j] = 0.f;

    for (int kt = 0; kt < SRC; kt += A1_BK) {
        __syncthreads();
        for (int i = tid; i < A1_BK * HD; i += 256) {
            int r = i / HD, d = i - r * HD;
            Ksm[r * A1_KP + d] = kvp[(size_t)(kt + r) * 544 + h * HD + d];
            Vsm[r * A1_KP + d] = kvp[(size_t)(kt + r) * 544 + EQ + h * HD + d];
        }
        __syncthreads();

        float sc[4][2];
#pragma unroll
        for (int i = 0; i < 4; i++) { sc[i][0] = 0.f; sc[i][1] = 0.f; }
        const float* krow0 = &Ksm[(txk * 2 + 0) * A1_KP];
        const float* krow1 = &Ksm[(txk * 2 + 1) * A1_KP];
#pragma unroll 4
        for (int d = 0; d < HD; d++) {
            float kv0 = krow0[d];
            float kv1 = krow1[d];
#pragma unroll
            for (int i = 0; i < 4; i++) {
                float qv = Qs[(tyq * 4 + i) * HD + d];
                sc[i][0] = fmaf(qv, kv0, sc[i][0]);
                sc[i][1] = fmaf(qv, kv1, sc[i][1]);
            }
        }
#pragma unroll
        for (int i = 0; i < 4; i++) {
            Ps[(tyq * 4 + i) * A1_PP + txk * 2 + 0] = sc[i][0];
            Ps[(tyq * 4 + i) * A1_PP + txk * 2 + 1] = sc[i][1];
        }
        __syncthreads();

        if (tid < A1_BQ) {
            float mx = m_s[tid];
            float* prow = &Ps[tid * A1_PP];
#pragma unroll 8
            for (int j = 0; j < A1_BK; j++) mx = fmaxf(mx, prow[j]);
            float al = expf(m_s[tid] - mx);
            float sum = 0.f;
#pragma unroll 8
            for (int j = 0; j < A1_BK; j++) {
                float e = expf(prow[j] - mx);
                prow[j] = e;
                sum += e;
            }
            l_s[tid] = l_s[tid] * al + sum;
            m_s[tid] = mx;
            al_s[tid] = al;
        }
        __syncthreads();

        float al = al_s[qown];
#pragma unroll
        for (int j = 0; j < 17; j++) oacc[j] *= al;
        const float* prow = &Ps[qown * A1_PP];
#pragma unroll 2
        for (int ki = 0; ki < A1_BK; ki++) {
            float p = prow[ki];
            const float* vrow = &Vsm[ki * A1_KP + dg * 17];
#pragma unroll
            for (int j = 0; j < 17; j++) oacc[j] = fmaf(p, vrow[j], oacc[j]);
        }
    }

    float inv = 1.f / l_s[qown];
#pragma unroll
    for (int j = 0; j < 17; j++)
        o[(size_t)(q0 + qown) * EQ + h * HD + dg * 17 + j] =
            __float2half(oacc[j] * inv);
}

// ---------------------------------------------------------------------------
// Host launch
// ---------------------------------------------------------------------------
static inline void launch_cvt(const float* in, __half* out, size_t n,
                              cudaStream_t s) {
    int n4 = (int)(n / 4);
    cvt16<<<(n4 + 255) / 256, 256, 0, s>>>(in, out, n4);
}

extern "C" void kernel_launch(void* const* d_in, const int* in_sizes, int n_in,
                              void* d_out, int out_size)
{
    const float* emb0  = (const float*)d_in[0];
    const float* edge0 = (const float*)d_in[1];
    const float* td0   = (const float*)d_in[2];
    const float* emb1  = (const float*)d_in[3];
    const float* edge1 = (const float*)d_in[4];
    const float* td1   = (const float*)d_in[5];
    const float* emb2  = (const float*)d_in[6];
    const float* Wq    = (const float*)d_in[7];
    const float* bq    = (const float*)d_in[8];
    const float* Wk    = (const float*)d_in[9];
    const float* bk    = (const float*)d_in[10];
    const float* Wv    = (const float*)d_in[11];
    const float* bv    = (const float*)d_in[12];
    const float* Wo    = (const float*)d_in[13];
    const float* bo    = (const float*)d_in[14];
    const float* W1    = (const float*)d_in[15];
    const float* b1    = (const float*)d_in[16];
    const float* W2    = (const float*)d_in[17];
    const float* b2    = (const float*)d_in[18];
    float* out = (float*)d_out;

    float *kvp0, *qp0, *kvp1, *qp1;
    cudaGetSymbolAddress((void**)&kvp0, g_kvp0);
    cudaGetSymbolAddress((void**)&qp0,  g_qp0);
    cudaGetSymbolAddress((void**)&kvp1, g_kvp1);
    cudaGetSymbolAddress((void**)&qp1,  g_qp1);

    __half *he0, *hg0, *ht0, *he1, *hg1, *ht1, *he2;
    __half *hWq, *hWk, *hWv, *hWo, *hW1, *hW2;
    __half *ho0, *ha0, *hh0, *ho1, *ha1, *hh1;
    cudaGetSymbolAddress((void**)&he0, hb_emb0);
    cudaGetSymbolAddress((void**)&hg0, hb_edge0);
    cudaGetSymbolAddress((void**)&ht0, hb_td0);
    cudaGetSymbolAddress((void**)&he1, hb_emb1);
    cudaGetSymbolAddress((void**)&hg1, hb_edge1);
    cudaGetSymbolAddress((void**)&ht1, hb_td1);
    cudaGetSymbolAddress((void**)&he2, hb_emb2);
    cudaGetSymbolAddress((void**)&hWq, hb_Wq);
    cudaGetSymbolAddress((void**)&hWk, hb_Wk);
    cudaGetSymbolAddress((void**)&hWv, hb_Wv);
    cudaGetSymbolAddress((void**)&hWo, hb_Wo);
    cudaGetSymbolAddress((void**)&hW1, hb_W1);
    cudaGetSymbolAddress((void**)&hW2, hb_W2);
    cudaGetSymbolAddress((void**)&ho0, hb_o0);
    cudaGetSymbolAddress((void**)&ha0, hb_a0);
    cudaGetSymbolAddress((void**)&hh0, hb_h0);
    cudaGetSymbolAddress((void**)&ho1, hb_o1);
    cudaGetSymbolAddress((void**)&ha1, hb_a1);
    cudaGetSymbolAddress((void**)&hh1, hb_h1);

    // static side stream + fork/join events (created once on the
    // correctness call, before graph capture; identical work every call)
    static cudaStream_t s2 = nullptr;
    static cudaEvent_t evFork = nullptr, evJoin = nullptr;
    if (s2 == nullptr) {
        cudaStreamCreateWithFlags(&s2, cudaStreamNonBlocking);
        cudaEventCreateWithFlags(&evFork, cudaEventDisableTiming);
        cudaEventCreateWithFlags(&evJoin, cudaEventDisableTiming);
    }
    cudaStream_t s0 = (cudaStream_t)0;   // legacy default (capture) stream

    const float scale = 1.0f / sqrtf((float)HD);
    const int smem1 = A1_SMEM_FLOATS * (int)sizeof(float);
    cudaFuncSetAttribute(attn1_kernel,
                         cudaFuncAttributeMaxDynamicSharedMemorySize, smem1);
    cudaFuncSetAttribute(gemm_mma<1, 1, false, false>,
                         cudaFuncAttributeMaxDynamicSharedMemorySize, GM_SMEM);
    cudaFuncSetAttribute(gemm_mma<2, 0, false, false>,
                         cudaFuncAttributeMaxDynamicSharedMemorySize, GM_SMEM);
    cudaFuncSetAttribute(gemm_mma<0, 0, false, true>,
                         cudaFuncAttributeMaxDynamicSharedMemorySize, GM_SMEM);
    cudaFuncSetAttribute(gemm_mma<3, 0, true, true>,
                         cudaFuncAttributeMaxDynamicSharedMemorySize, GM_SMEM);
    cudaFuncSetAttribute(gemm_mma<0, 0, false, false>,
                         cudaFuncAttributeMaxDynamicSharedMemorySize, GM_SMEM);

    // ---------------- fp16 conversions (main stream) ----------------
    launch_cvt(emb0,  he0, (size_t)SRC*NB*NB*DDIM, s0);
    launch_cvt(edge0, hg0, (size_t)SRC*NB*NB*EDIM, s0);
    launch_cvt(td0,   ht0, (size_t)SRC*NB*NB*TDIM, s0);
    launch_cvt(emb1,  he1, (size_t)SRC*NB*DDIM, s0);
    launch_cvt(edge1, hg1, (size_t)SRC*NB*EDIM, s0);
    launch_cvt(td1,   ht1, (size_t)SRC*NB*TDIM, s0);
    launch_cvt(emb2,  he2, (size_t)SRC*DDIM, s0);
    launch_cvt(Wq, hWq, (size_t)EQ*EQ, s0);
    launch_cvt(Wk, hWk, (size_t)EQ*KDT, s0);
    launch_cvt(Wv, hWv, (size_t)EQ*KDT, s0);
    launch_cvt(Wo, hWo, (size_t)EQ*EQ, s0);
    launch_cvt(W1, hW1, (size_t)DDIM*(EQ+DDIM), s0);
    launch_cvt(W2, hW2, (size_t)DDIM*DDIM, s0);

    // ---------------- fork ----------------
    cudaEventRecord(evFork, s0);
    cudaStreamWaitEvent(s2, evFork, 0);

    // ---------------- propagation 1 + passthrough (side stream) ---------
    cudaMemcpyAsync(out + OUT_EDGE, edge1,
                    (size_t)SRC * NB * EDIM * sizeof(float),
                    cudaMemcpyDeviceToDevice, s2);
    cudaMemcpyAsync(out + OUT_TD, td1,
                    (size_t)SRC * NB * TDIM * sizeof(float),
                    cudaMemcpyDeviceToDevice, s2);
    gemm_mma<1, 1, false, false><<<dim3(9, 16), 256, GM_SMEM, s2>>>(
        he1, hg1, ht1, 0, hWk, hWv, KDT, bk, bv,
        kvp1, M1, 544, KDT, 544, 1.f);
    gemm_mma<0, 0, false, false><<<dim3(5, 16), 256, GM_SMEM, s2>>>(
        he2, nullptr, nullptr, DDIM, hWq, nullptr, EQ, bq, nullptr,
        qp1, M1, EQ, DDIM, EQ, scale);
    attn1_kernel<<<dim3(SRC / A1_BQ, 2), 256, smem1, s2>>>(qp1, kvp1, ho1);
    gemm_mma<0, 0, false, true><<<dim3(5, 16), 256, GM_SMEM, s2>>>(
        ho1, nullptr, nullptr, EQ, hWo, nullptr, EQ, bo, nullptr,
        ha1, M1, EQ, EQ, EQ, 1.f);
    gemm_mma<3, 0, true, true><<<dim3(3, 16), 256, GM_SMEM, s2>>>(
        ha1, he2, nullptr, 0, hW1, nullptr, EQ + DDIM, b1, nullptr,
        hh1, M1, DDIM, EQ + DDIM, DDIM, 1.f);
    gemm_mma<0, 0, false, false><<<dim3(3, 16), 256, GM_SMEM, s2>>>(
        hh1, nullptr, nullptr, DDIM, hW2, nullptr, DDIM, b2, nullptr,
        out + OUT_R1, M1, DDIM, DDIM, DDIM, 1.f);
    cudaEventRecord(evJoin, s2);

    // ---------------- propagation 0 (main stream) ----------------
    gemm_mma<1, 1, false, false><<<dim3(9, 160), 256, GM_SMEM, s0>>>(
        he0, hg0, ht0, 0, hWk, hWv, KDT, bk, bv,
        kvp0, M0, 544, KDT, 544, 1.f);
    gemm_mma<2, 0, false, false><<<dim3(5, 160), 256, GM_SMEM, s0>>>(
        he1, ht1, nullptr, 0, hWq, nullptr, EQ, bq, nullptr,
        qp0, M0, EQ, EQ, EQ, scale);
    attn0_kernel<<<SRC, 256, 0, s0>>>(qp0, kvp0, ho0);
    gemm_mma<0, 0, false, true><<<dim3(5, 160), 256, GM_SMEM, s0>>>(
        ho0, nullptr, nullptr, EQ, hWo, nullptr, EQ, bo, nullptr,
        ha0, M0, EQ, EQ, EQ, 1.f);
    gemm_mma<3, 0, true, true><<<dim3(3, 160), 256, GM_SMEM, s0>>>(
        ha0, he1, nullptr, 0, hW1, nullptr, EQ + DDIM, b1, nullptr,
        hh0, M0, DDIM, EQ + DDIM, DDIM, 1.f);
    gemm_mma<0, 0, false, false><<<dim3(3, 160), 256, GM_SMEM, s0>>>(
        hh0, nullptr, nullptr, DDIM, hW2, nullptr, DDIM, b2, nullptr,
        out + OUT_R0, M0, DDIM, DDIM, DDIM, 1.f);

    // ---------------- join ----------------
    cudaStreamWaitEvent(s0, evJoin, 0);
}